// round 8
// baseline (speedup 1.0000x reference)
#include <cuda_runtime.h>
#include <cuda_bf16.h>
#include <cstdint>

// Problem constants
#define BATCH 8
#define SEQ   4096
#define DIM   512
#define HEADS 8
#define DH    64
#define INNER 512          // HEADS*DH
#define QKV_COLS 1536      // 3*INNER
#define ROWS  (BATCH*SEQ)  // 32768
#define EPS   1e-5f

// ---------------------------------------------------------------------------
// Scratch (device globals; no allocation allowed)
// ---------------------------------------------------------------------------
__device__ float g_qkv[(size_t)ROWS * QKV_COLS];            // 201 MB fp32 q|k|v
__device__ __nv_bfloat16 g_xh[(size_t)ROWS * DIM];          // 32 MB each
__device__ __nv_bfloat16 g_xl[(size_t)ROWS * DIM];
__device__ __nv_bfloat16 g_wh[(size_t)QKV_COLS * DIM];      // 1.5 MB
__device__ __nv_bfloat16 g_wl[(size_t)QKV_COLS * DIM];
__device__ __nv_bfloat16 g_qh[(size_t)ROWS * INNER];        // post LN/RoPE hi/lo
__device__ __nv_bfloat16 g_ql[(size_t)ROWS * INNER];
__device__ __nv_bfloat16 g_kh[(size_t)ROWS * INNER];
__device__ __nv_bfloat16 g_kl[(size_t)ROWS * INNER];
__device__ __nv_bfloat16 g_vh[(size_t)ROWS * INNER];
__device__ __nv_bfloat16 g_vl[(size_t)ROWS * INNER];
__device__ __nv_bfloat16 g_mh[(size_t)BATCH * DIM * INNER]; // 4 MB
__device__ __nv_bfloat16 g_ml[(size_t)BATCH * DIM * INNER];
__device__ float g_dots[BATCH * HEADS * DH * DH];           // 1 MB

// ---------------------------------------------------------------------------
// PTX primitives (arch-agnostic; safe under .target sm_103)
// ---------------------------------------------------------------------------
__device__ __forceinline__ void cp16(uint32_t sdst, const void* gsrc) {
    asm volatile("cp.async.cg.shared.global [%0], [%1], 16;"
                 :: "r"(sdst), "l"(gsrc) : "memory");
}
__device__ __forceinline__ void cp_commit() {
    asm volatile("cp.async.commit_group;" ::: "memory");
}
template <int N> __device__ __forceinline__ void cp_wait() {
    asm volatile("cp.async.wait_group %0;" :: "n"(N) : "memory");
}
__device__ __forceinline__ void ldsm4(uint32_t* r, uint32_t a) {
    asm volatile("ldmatrix.sync.aligned.m8n8.x4.shared.b16 {%0,%1,%2,%3}, [%4];"
                 : "=r"(r[0]), "=r"(r[1]), "=r"(r[2]), "=r"(r[3]) : "r"(a));
}
__device__ __forceinline__ void ldsm4t(uint32_t* r, uint32_t a) {
    asm volatile("ldmatrix.sync.aligned.m8n8.x4.trans.shared.b16 {%0,%1,%2,%3}, [%4];"
                 : "=r"(r[0]), "=r"(r[1]), "=r"(r[2]), "=r"(r[3]) : "r"(a));
}
__device__ __forceinline__ void mma16816(float* c, const uint32_t* a, const uint32_t* b) {
    asm volatile(
        "mma.sync.aligned.m16n8k16.row.col.f32.bf16.bf16.f32 "
        "{%0,%1,%2,%3}, {%4,%5,%6,%7}, {%8,%9}, {%0,%1,%2,%3};"
        : "+f"(c[0]), "+f"(c[1]), "+f"(c[2]), "+f"(c[3])
        : "r"(a[0]), "r"(a[1]), "r"(a[2]), "r"(a[3]), "r"(b[0]), "r"(b[1]));
}
__device__ __forceinline__ float warp_sum(float v) {
#pragma unroll
    for (int o = 16; o > 0; o >>= 1) v += __shfl_xor_sync(0xffffffffu, v, o);
    return v;
}

// ---------------------------------------------------------------------------
// Big-GEMM machinery: 128x128 tile, BK=32, 2-stage buffers but HALF-STAGE
// commit groups (4 groups in flight). 2 CTAs/SM, 1 sync per K-iteration.
// ---------------------------------------------------------------------------
#define BK 32
#define SROW 40                        // padded smem row (bf16) = 80B
#define SROWB (SROW * 2)
#define MAT_BYTES (128 * SROW * 2)     // 10240
#define STAGE_BYTES (4 * MAT_BYTES)    // Ah|Al|Bh|Bl = 40960
#define GEMM_SMEM (2 * STAGE_BYTES)    // 81920

// Load one 16-col half of a BK=32 stage (half = 0 or 1). 4 cp16 per thread.
__device__ __forceinline__ void stage_load_half(uint32_t sbase,
                                                const __nv_bfloat16* __restrict__ Ah,
                                                const __nv_bfloat16* __restrict__ Al,
                                                const __nv_bfloat16* __restrict__ Bh,
                                                const __nv_bfloat16* __restrict__ Bl,
                                                int k0, int half, int tid) {
    int row = tid >> 1;
    int c8 = half * 2 + (tid & 1);
    uint32_t so = sbase + (uint32_t)(row * SROWB + c8 * 16);
    size_t go = (size_t)row * 512 + k0 + c8 * 8;
    cp16(so,                 Ah + go);
    cp16(so + MAT_BYTES,     Al + go);
    cp16(so + 2 * MAT_BYTES, Bh + go);
    cp16(so + 3 * MAT_BYTES, Bl + go);
}

// One kk-halfstep of compute (kk = 0 or 1) on stage buffer sb.
__device__ __forceinline__ void compute_half(uint32_t sb, int kk,
                                             uint32_t a_lane_off,
                                             int b4_row, uint32_t b4_colh,
                                             float acc[4][4][4]) {
    uint32_t bh[2][4], bl2[2][4];
#pragma unroll
    for (int nip = 0; nip < 2; nip++) {
        uint32_t bd = sb + 2 * MAT_BYTES +
                      (uint32_t)((b4_row + nip * 16) * SROWB) + b4_colh +
                      (uint32_t)(kk * 32);
        ldsm4(bh[nip], bd);
        ldsm4(bl2[nip], bd + MAT_BYTES);
    }
#pragma unroll
    for (int mi = 0; mi < 4; mi++) {
        uint32_t ah[4], al2[4];
        uint32_t ad = sb + a_lane_off + (uint32_t)(mi * 16 * SROWB + kk * 32);
        ldsm4(ah, ad);
        ldsm4(al2, ad + MAT_BYTES);
#pragma unroll
        for (int ni = 0; ni < 4; ni++) {
            const uint32_t* bhf = &bh[ni >> 1][(ni & 1) * 2];
            const uint32_t* blf = &bl2[ni >> 1][(ni & 1) * 2];
            mma16816(acc[mi][ni], ah, bhf);
            mma16816(acc[mi][ni], ah, blf);
            mma16816(acc[mi][ni], al2, bhf);
        }
    }
}

// Fills acc[4][4][4]; warp tile 64x32 (wm=wid>>2, wn=wid&3).
__device__ __forceinline__ void tc_mainloop(const __nv_bfloat16* __restrict__ Ah,
                                            const __nv_bfloat16* __restrict__ Al,
                                            const __nv_bfloat16* __restrict__ Bh,
                                            const __nv_bfloat16* __restrict__ Bl,
                                            float acc[4][4][4]) {
    extern __shared__ char sm[];
    const uint32_t sbase = (uint32_t)__cvta_generic_to_shared(sm);
    const int tid = threadIdx.x;
    const int lane = tid & 31;
    const int wid = tid >> 5;
    const int wm = wid >> 2;
    const int wn = wid & 3;
    const int la = lane & 15;
    const uint32_t a_lane_off = (uint32_t)((wm * 64 + la) * SROWB + (lane >> 4) * 16);
    const int b4_row = wn * 32 + ((lane >> 4) * 8) + (lane & 7);
    const uint32_t b4_colh = (uint32_t)(((lane >> 3) & 1) * 16);

#pragma unroll
    for (int mi = 0; mi < 4; mi++)
#pragma unroll
        for (int ni = 0; ni < 4; ni++)
#pragma unroll
            for (int j = 0; j < 4; j++) acc[mi][ni][j] = 0.0f;

    stage_load_half(sbase, Ah, Al, Bh, Bl, 0, 0, tid);
    cp_commit();
    stage_load_half(sbase, Ah, Al, Bh, Bl, 0, 1, tid);
    cp_commit();

    for (int c = 0; c < 16; c++) {
        __syncthreads();     // all warps done reading buffer (c+1)&1 (= c-1's data)
        const uint32_t sb = sbase + (uint32_t)((c & 1) * STAGE_BYTES);
        if (c < 15) {
            const uint32_t nb = sbase + (uint32_t)(((c + 1) & 1) * STAGE_BYTES);
            stage_load_half(nb, Ah, Al, Bh, Bl, (c + 1) * BK, 0, tid);
            cp_commit();
            stage_load_half(nb, Ah, Al, Bh, Bl, (c + 1) * BK, 1, tid);
            cp_commit();
            cp_wait<3>();    // stage-c half0 landed
            compute_half(sb, 0, a_lane_off, b4_row, b4_colh, acc);
            cp_wait<2>();    // stage-c half1 landed
            compute_half(sb, 1, a_lane_off, b4_row, b4_colh, acc);
        } else {
            cp_wait<1>();
            compute_half(sb, 0, a_lane_off, b4_row, b4_colh, acc);
            cp_wait<0>();
            compute_half(sb, 1, a_lane_off, b4_row, b4_colh, acc);
        }
    }
}

// ---------------------------------------------------------------------------
// QKV GEMM -> fp32 g_qkv (plain epilogue; LN/RoPE handled downstream)
// ---------------------------------------------------------------------------
__global__ __launch_bounds__(256, 2) void gemm_qkv_tc(void) {
    const size_t bm = (size_t)blockIdx.y * 128, bn = (size_t)blockIdx.x * 128;

    float acc[4][4][4];
    tc_mainloop(g_xh + bm * 512, g_xl + bm * 512,
                g_wh + bn * 512, g_wl + bn * 512, acc);

    const int tid = threadIdx.x;
    const int lane = tid & 31;
    const int wid = tid >> 5;
    const int wm = wid >> 2, wn = wid & 3;
    const int r0 = lane >> 2, c0 = (lane & 3) * 2;
    float* C = g_qkv + bm * QKV_COLS + bn;

#pragma unroll
    for (int mi = 0; mi < 4; mi++)
#pragma unroll
        for (int ni = 0; ni < 4; ni++) {
            int row = wm * 64 + mi * 16 + r0;
            int col = wn * 32 + ni * 8 + c0;
            *(float2*)(C + (size_t)row * QKV_COLS + col) =
                make_float2(acc[mi][ni][0], acc[mi][ni][1]);
            *(float2*)(C + (size_t)(row + 8) * QKV_COLS + col) =
                make_float2(acc[mi][ni][2], acc[mi][ni][3]);
        }
}

// ---------------------------------------------------------------------------
// Output GEMM: out[b] = q[b] @ McatT[b]^T + bias
// ---------------------------------------------------------------------------
__global__ __launch_bounds__(256, 2) void gemm_out_tc(const float* __restrict__ bout,
                                                      float* __restrict__ out) {
    const int b = blockIdx.z;
    const size_t arow = (size_t)b * SEQ + (size_t)blockIdx.y * 128;
    const size_t brow = (size_t)b * DIM + (size_t)blockIdx.x * 128;

    float acc[4][4][4];
    tc_mainloop(g_qh + arow * 512, g_ql + arow * 512,
                g_mh + brow * 512, g_ml + brow * 512, acc);

    const int tid = threadIdx.x;
    const int lane = tid & 31;
    const int wid = tid >> 5;
    const int wm = wid >> 2, wn = wid & 3;
    const int r0 = lane >> 2, c0 = (lane & 3) * 2;
    float* C = out + arow * DIM + blockIdx.x * 128;
    const float* bias = bout + blockIdx.x * 128;

#pragma unroll
    for (int mi = 0; mi < 4; mi++)
#pragma unroll
        for (int ni = 0; ni < 4; ni++) {
            int row = wm * 64 + mi * 16 + r0;
            int col = wn * 32 + ni * 8 + c0;
            float b0 = bias[col], b1 = bias[col + 1];
            *(float2*)(C + (size_t)row * DIM + col) =
                make_float2(acc[mi][ni][0] + b0, acc[mi][ni][1] + b1);
            *(float2*)(C + (size_t)(row + 8) * DIM + col) =
                make_float2(acc[mi][ni][2] + b0, acc[mi][ni][3] + b1);
        }
}

// ---------------------------------------------------------------------------
// bf16 hi/lo split (x and Wqkv)
// ---------------------------------------------------------------------------
__global__ __launch_bounds__(256) void split_kernel(const float* __restrict__ src,
                                                    __nv_bfloat16* __restrict__ hi,
                                                    __nv_bfloat16* __restrict__ lo,
                                                    int n4) {
    int i = blockIdx.x * 256 + threadIdx.x;
    if (i >= n4) return;
    float4 v = ((const float4*)src)[i];
    size_t idx = (size_t)i * 4;
    __nv_bfloat16 hx = __float2bfloat16(v.x), hy = __float2bfloat16(v.y);
    __nv_bfloat16 hz = __float2bfloat16(v.z), hw = __float2bfloat16(v.w);
    hi[idx + 0] = hx; hi[idx + 1] = hy; hi[idx + 2] = hz; hi[idx + 3] = hw;
    lo[idx + 0] = __float2bfloat16(v.x - __bfloat162float(hx));
    lo[idx + 1] = __float2bfloat16(v.y - __bfloat162float(hy));
    lo[idx + 2] = __float2bfloat16(v.z - __bfloat162float(hz));
    lo[idx + 3] = __float2bfloat16(v.w - __bfloat162float(hw));
}

// ---------------------------------------------------------------------------
// LN(k,v) + RoPE(q,k) reading fp32 g_qkv, writing bf16 hi/lo q/k/v directly.
// One warp per (b,n,h) row.
// ---------------------------------------------------------------------------
__global__ __launch_bounds__(256) void ln_rope_split_kernel(
        const float* __restrict__ pos,
        const float* __restrict__ gk, const float* __restrict__ bk,
        const float* __restrict__ gv, const float* __restrict__ bv) {
    const int warp = threadIdx.x >> 5;
    const int lane = threadIdx.x & 31;
    const int r = blockIdx.x * 8 + warp;     // 0 .. B*N*H-1
    const int b = r >> 15;
    const int rem = r & 32767;
    const int n = rem >> 3;
    const int h = rem & 7;
    const int token = b * SEQ + n;

    const float* qp = g_qkv + (size_t)token * QKV_COLS + h * DH;
    const float* kp = qp + INNER;
    const float* vp = qp + 2 * INNER;

    float q0 = qp[lane], q1 = qp[lane + 32];
    float k0 = kp[lane], k1 = kp[lane + 32];
    float v0 = vp[lane], v1 = vp[lane + 32];

    // LayerNorm k
    float mu = warp_sum(k0 + k1) * (1.0f / 64.0f);
    float d0 = k0 - mu, d1 = k1 - mu;
    float var = warp_sum(d0 * d0 + d1 * d1) * (1.0f / 64.0f);
    float inv = rsqrtf(var + EPS);
    k0 = d0 * inv * gk[lane] + bk[lane];
    k1 = d1 * inv * gk[lane + 32] + bk[lane + 32];

    // LayerNorm v
    mu = warp_sum(v0 + v1) * (1.0f / 64.0f);
    d0 = v0 - mu; d1 = v1 - mu;
    var = warp_sum(d0 * d0 + d1 * d1) * (1.0f / 64.0f);
    inv = rsqrtf(var + EPS);
    v0 = d0 * inv * gv[lane] + bv[lane];
    v1 = d1 * inv * gv[lane + 32] + bv[lane + 32];

    // 2D RoPE on q,k
    const float cxp = pos[(size_t)token * 2 + 0];
    const float cyp = pos[(size_t)token * 2 + 1];
    float invf = exp2f(-0.830482023721841f * (float)(lane & 15)) * 64.0f;
    float sx, cx, sy, cy;
    sincosf(cxp * invf, &sx, &cx);
    sincosf(cyp * invf, &sy, &cy);
    const float sgn = (lane < 16) ? -1.0f : 1.0f;

    float qp0 = __shfl_xor_sync(0xffffffffu, q0, 16);
    float qp1 = __shfl_xor_sync(0xffffffffu, q1, 16);
    float kp0 = __shfl_xor_sync(0xffffffffu, k0, 16);
    float kp1 = __shfl_xor_sync(0xffffffffu, k1, 16);
    q0 = q0 * cx + sgn * qp0 * sx;
    q1 = q1 * cy + sgn * qp1 * sy;
    k0 = k0 * cx + sgn * kp0 * sx;
    k1 = k1 * cy + sgn * kp1 * sy;

    // write bf16 hi/lo, layout token*512 + h*64 + d
    const size_t base = (size_t)token * 512 + h * DH;
#define WR(arr_h, arr_l, a0, a1)                                            \
    {                                                                       \
        __nv_bfloat16 h0 = __float2bfloat16(a0);                            \
        __nv_bfloat16 h1 = __float2bfloat16(a1);                            \
        arr_h[base + lane] = h0;                                            \
        arr_h[base + 32 + lane] = h1;                                       \
        arr_l[base + lane] = __float2bfloat16(a0 - __bfloat162float(h0));   \
        arr_l[base + 32 + lane] = __float2bfloat16(a1 - __bfloat162float(h1)); \
    }
    WR(g_qh, g_ql, q0, q1)
    WR(g_kh, g_kl, k0, k1)
    WR(g_vh, g_vl, v0, v1)
#undef WR
}

// ---------------------------------------------------------------------------
// dots = K^T V via HMMA (3-pass split), K-major loads via ldmatrix.trans.
// grid (64 bh, 4 splits of 1024 tokens). 128 threads = 4 warps (2x2 of 32x32).
// ---------------------------------------------------------------------------
#define KV_SR 72                       // bf16 elems per row = 144B
#define KV_TILE (64 * KV_SR * 2)       // 9216
#define KV_STAGE (4 * KV_TILE)         // 36864
#define KV_SMEM (3 * KV_STAGE)         // 110592

__device__ __forceinline__ void kv_stage_load(uint32_t sb, int b, int h, int tok0,
                                              int tid) {
#pragma unroll
    for (int hh = 0; hh < 16; hh++) {
        int i = tid + hh * 128;        // 0..2047
        int op = i >> 9;
        int ii = i & 511;
        int row = ii >> 3, ch = ii & 7;
        const __nv_bfloat16* src = (op == 0) ? g_kh : (op == 1) ? g_kl
                                 : (op == 2) ? g_vh : g_vl;
        cp16(sb + (uint32_t)(op * KV_TILE + row * (KV_SR * 2) + ch * 16),
             src + ((size_t)(b * SEQ + tok0 + row)) * 512 + h * 64 + ch * 8);
    }
}

__global__ __launch_bounds__(128) void kv_dots_kernel() {
    extern __shared__ char sm[];
    const uint32_t sbase = (uint32_t)__cvta_generic_to_shared(sm);
    const int bh = blockIdx.x;
    const int b = bh >> 3, h = bh & 7;
    const int tok0 = blockIdx.y * 1024;
    const int tid = threadIdx.x;
    const int lane = tid & 31;
    const int wid = tid >> 5;
    const int wm = wid >> 1;
    const int wn = wid & 1;

    const int t_row = (lane & 7) + ((lane >> 4) & 1) * 8;
    const int a_col = ((lane >> 3) & 1) * 8;
    const int b_row = (lane & 7) + ((lane >> 3) & 1) * 8;
    const int b_col = (lane >> 4) * 8;

    float acc[2][4][4];
#pragma unroll
    for (int mf = 0; mf < 2; mf++)
#pragma unroll
        for (int nf = 0; nf < 4; nf++)
#pragma unroll
            for (int j = 0; j < 4; j++) acc[mf][nf][j] = 0.0f;

    kv_stage_load(sbase, b, h, tok0, tid);
    cp_commit();
    kv_stage_load(sbase + KV_STAGE, b, h, tok0 + 64, tid);
    cp_commit();

    for (int s = 0; s < 16; s++) {
        if (s < 15) cp_wait<1>(); else cp_wait<0>();
        __syncthreads();
        if (s + 2 < 16) {
            kv_stage_load(sbase + (uint32_t)(((s + 2) % 3) * KV_STAGE),
                          b, h, tok0 + (s + 2) * 64, tid);
            cp_commit();
        }
        const uint32_t sb = sbase + (uint32_t)((s % 3) * KV_STAGE);
#pragma unroll
        for (int kt = 0; kt < 4; kt++) {
            const int kt0 = kt * 16;
            uint32_t aH[2][4], aL[2][4], bH[2][4], bL[2][4];
#pragma unroll
            for (int mf = 0; mf < 2; mf++) {
                int d0 = wm * 32 + mf * 16;
                uint32_t ad = sb + (uint32_t)((kt0 + t_row) * (KV_SR * 2) +
                                              (d0 + a_col) * 2);
                ldsm4t(aH[mf], ad);
                ldsm4t(aL[mf], ad + KV_TILE);
            }
#pragma unroll
            for (int g = 0; g < 2; g++) {
                int e0 = wn * 32 + g * 16;
                uint32_t bd = sb + 2 * KV_TILE +
                              (uint32_t)((kt0 + b_row) * (KV_SR * 2) +
                                         (e0 + b_col) * 2);
                ldsm4t(bH[g], bd);
                ldsm4t(bL[g], bd + KV_TILE);
            }
#pragma unroll
            for (int mf = 0; mf < 2; mf++)
#pragma unroll
                for (int nf = 0; nf < 4; nf++) {
                    const uint32_t* bhf = &bH[nf >> 1][(nf & 1) * 2];
                    const uint32_t* blf = &bL[nf >> 1][(nf & 1) * 2];
                    mma16816(acc[mf][nf], aH[mf], bhf);
                    mma16816(acc[mf][nf], aH[mf], blf);
                    mma16816(acc[mf][nf], aL[mf], bhf);
                }
        }
    }

    float* dbase = g_dots + (size_t)bh * DH * DH;
    const int r0 = lane >> 2, c0 = (lane & 3) * 2;
#pragma unroll
    for (int mf = 0; mf < 2; mf++)
#pragma unroll
        for (int nf = 0; nf < 4; nf++) {
            int d = wm * 32 + mf * 16 + r0;
            int e = wn * 32 + nf * 8 + c0;
            atomicAdd(&dbase[d * DH + e],       acc[mf][nf][0]);
            atomicAdd(&dbase[d * DH + e + 1],   acc[mf][nf][1]);
            atomicAdd(&dbase[(d + 8) * DH + e],     acc[mf][nf][2]);
            atomicAdd(&dbase[(d + 8) * DH + e + 1], acc[mf][nf][3]);
        }
}

__global__ void zero_dots_kernel() {
    g_dots[blockIdx.x * blockDim.x + threadIdx.x] = 0.0f;
}

// ---------------------------------------------------------------------------
// McatT[b][o, h*64+d] = (1/SEQ) * sum_e dots[b,h,d,e] * Wout[o, h*64+e]
// ---------------------------------------------------------------------------
__global__ __launch_bounds__(256) void mcat_kernel(const float* __restrict__ Wout) {
    __shared__ float ds[64][65];
    __shared__ float ws[64][65];

    const int bh = blockIdx.x;
    const int b = bh >> 3, h = bh & 7;
    const int o0 = blockIdx.y * 64;
    const int tid = threadIdx.x;

    for (int i = tid; i < 4096; i += 256) {
        int d = i >> 6, e = i & 63;
        ds[d][e] = g_dots[(size_t)bh * 4096 + i];
        ws[d][e] = Wout[(size_t)(o0 + d) * INNER + h * DH + e];
    }
    __syncthreads();

    for (int t = tid; t < 4096; t += 256) {
        int oL = t >> 6, d = t & 63;
        float acc = 0.0f;
#pragma unroll
        for (int e = 0; e < 64; e++) acc += ds[d][e] * ws[oL][e];
        acc *= (1.0f / (float)SEQ);
        size_t idx = ((size_t)b * DIM + (o0 + oL)) * 512 + h * DH + d;
        __nv_bfloat16 hi = __float2bfloat16(acc);
        g_mh[idx] = hi;
        g_ml[idx] = __float2bfloat16(acc - __bfloat162float(hi));
    }
}

// ---------------------------------------------------------------------------
// launch
// ---------------------------------------------------------------------------
extern "C" void kernel_launch(void* const* d_in, const int* in_sizes, int n_in,
                              void* d_out, int out_size) {
    const float* x    = (const float*)d_in[0];
    const float* pos  = (const float*)d_in[1];
    const float* Wqkv = (const float*)d_in[2];
    const float* gk   = (const float*)d_in[3];
    const float* bk   = (const float*)d_in[4];
    const float* gv   = (const float*)d_in[5];
    const float* bv   = (const float*)d_in[6];
    const float* Wout = (const float*)d_in[7];
    const float* bout = (const float*)d_in[8];
    float* out = (float*)d_out;

    static bool attr_done = false;
    if (!attr_done) {
        cudaFuncSetAttribute(gemm_qkv_tc,  cudaFuncAttributeMaxDynamicSharedMemorySize, GEMM_SMEM);
        cudaFuncSetAttribute(gemm_out_tc,  cudaFuncAttributeMaxDynamicSharedMemorySize, GEMM_SMEM);
        cudaFuncSetAttribute(kv_dots_kernel, cudaFuncAttributeMaxDynamicSharedMemorySize, KV_SMEM);
        attr_done = true;
    }

    void* p_xh; void* p_xl; void* p_wh; void* p_wl;
    cudaGetSymbolAddress(&p_xh, g_xh); cudaGetSymbolAddress(&p_xl, g_xl);
    cudaGetSymbolAddress(&p_wh, g_wh); cudaGetSymbolAddress(&p_wl, g_wl);

    // 1) hi/lo splits + dots zero
    int n4x = (ROWS * DIM) / 4;
    split_kernel<<<(n4x + 255) / 256, 256>>>(x, (__nv_bfloat16*)p_xh,
                                             (__nv_bfloat16*)p_xl, n4x);
    int n4w = (QKV_COLS * DIM) / 4;
    split_kernel<<<(n4w + 255) / 256, 256>>>(Wqkv, (__nv_bfloat16*)p_wh,
                                             (__nv_bfloat16*)p_wl, n4w);
    zero_dots_kernel<<<(BATCH * HEADS * DH * DH) / 256, 256>>>();

    // 2) qkv = x @ Wqkv^T (HMMA split-bf16) -> fp32 g_qkv
    gemm_qkv_tc<<<dim3(QKV_COLS / 128, ROWS / 128), 256, GEMM_SMEM>>>();

    // 3) LN(k,v) + RoPE(q,k) + hi/lo split -> g_{q,k,v}{h,l}
    ln_rope_split_kernel<<<(BATCH * SEQ * HEADS) / 8, 256>>>(pos, gk, bk, gv, bv);

    // 4) dots = K^T V (HMMA, atomic over 4 splits)
    kv_dots_kernel<<<dim3(BATCH * HEADS, 4), 128, KV_SMEM>>>();

    // 5) McatT[b] = (dots[b] @ Wout^T)/SEQ (bf16 hi/lo)
    mcat_kernel<<<dim3(BATCH * HEADS, DIM / 64), 256>>>(Wout);

    // 6) out[b] = q[b] @ McatT[b]^T + b_out
    gemm_out_tc<<<dim3(DIM / 128, SEQ / 128, BATCH), 256, GEMM_SMEM>>>(bout, out);
}

// round 9
// speedup vs baseline: 1.1606x; 1.1606x over previous
#include <cuda_runtime.h>
#include <cuda_bf16.h>
#include <cstdint>

// Problem constants
#define BATCH 8
#define SEQ   4096
#define DIM   512
#define HEADS 8
#define DH    64
#define INNER 512          // HEADS*DH
#define QKV_COLS 1536      // 3*INNER
#define ROWS  (BATCH*SEQ)  // 32768
#define EPS   1e-5f

// ---------------------------------------------------------------------------
// Scratch (device globals; no allocation allowed)
// ---------------------------------------------------------------------------
__device__ float g_qkv[(size_t)ROWS * QKV_COLS];            // 201 MB fp32 q|k|v
__device__ __nv_bfloat16 g_xh[(size_t)ROWS * DIM];          // 32 MB each
__device__ __nv_bfloat16 g_xl[(size_t)ROWS * DIM];
__device__ __nv_bfloat16 g_wh[(size_t)QKV_COLS * DIM];      // 1.5 MB
__device__ __nv_bfloat16 g_wl[(size_t)QKV_COLS * DIM];
__device__ __nv_bfloat16 g_qh[(size_t)ROWS * INNER];        // post LN/RoPE hi/lo
__device__ __nv_bfloat16 g_ql[(size_t)ROWS * INNER];
__device__ __nv_bfloat16 g_kh[(size_t)ROWS * INNER];
__device__ __nv_bfloat16 g_kl[(size_t)ROWS * INNER];
__device__ __nv_bfloat16 g_vh[(size_t)ROWS * INNER];
__device__ __nv_bfloat16 g_vl[(size_t)ROWS * INNER];
__device__ __nv_bfloat16 g_mh[(size_t)BATCH * DIM * INNER]; // 4 MB
__device__ __nv_bfloat16 g_ml[(size_t)BATCH * DIM * INNER];
__device__ float g_dots[BATCH * HEADS * DH * DH];           // 1 MB

// ---------------------------------------------------------------------------
// PTX primitives (arch-agnostic; safe under .target sm_103)
// ---------------------------------------------------------------------------
__device__ __forceinline__ void cp16(uint32_t sdst, const void* gsrc) {
    asm volatile("cp.async.cg.shared.global [%0], [%1], 16;"
                 :: "r"(sdst), "l"(gsrc) : "memory");
}
__device__ __forceinline__ void cp_commit() {
    asm volatile("cp.async.commit_group;" ::: "memory");
}
template <int N> __device__ __forceinline__ void cp_wait() {
    asm volatile("cp.async.wait_group %0;" :: "n"(N) : "memory");
}
__device__ __forceinline__ void ldsm4(uint32_t* r, uint32_t a) {
    asm volatile("ldmatrix.sync.aligned.m8n8.x4.shared.b16 {%0,%1,%2,%3}, [%4];"
                 : "=r"(r[0]), "=r"(r[1]), "=r"(r[2]), "=r"(r[3]) : "r"(a));
}
__device__ __forceinline__ void ldsm4t(uint32_t* r, uint32_t a) {
    asm volatile("ldmatrix.sync.aligned.m8n8.x4.trans.shared.b16 {%0,%1,%2,%3}, [%4];"
                 : "=r"(r[0]), "=r"(r[1]), "=r"(r[2]), "=r"(r[3]) : "r"(a));
}
__device__ __forceinline__ void mma16816(float* c, const uint32_t* a, const uint32_t* b) {
    asm volatile(
        "mma.sync.aligned.m16n8k16.row.col.f32.bf16.bf16.f32 "
        "{%0,%1,%2,%3}, {%4,%5,%6,%7}, {%8,%9}, {%0,%1,%2,%3};"
        : "+f"(c[0]), "+f"(c[1]), "+f"(c[2]), "+f"(c[3])
        : "r"(a[0]), "r"(a[1]), "r"(a[2]), "r"(a[3]), "r"(b[0]), "r"(b[1]));
}
__device__ __forceinline__ float warp_sum(float v) {
#pragma unroll
    for (int o = 16; o > 0; o >>= 1) v += __shfl_xor_sync(0xffffffffu, v, o);
    return v;
}

// ---------------------------------------------------------------------------
// Big-GEMM machinery: 128x128 tile, BK=32, 2-stage cp.async pipeline,
// 2 CTAs/SM, 1 sync/iter. ILP: pass-reordered MMAs + A-frag double buffer.
// ---------------------------------------------------------------------------
#define BK 32
#define SROW 40                        // padded smem row (bf16) = 80B
#define SROWB (SROW * 2)
#define MAT_BYTES (128 * SROW * 2)     // 10240
#define STAGE_BYTES (4 * MAT_BYTES)    // Ah|Al|Bh|Bl = 40960
#define GEMM_SMEM (2 * STAGE_BYTES)    // 81920

__device__ __forceinline__ void stage_load(uint32_t sbase,
                                           const __nv_bfloat16* __restrict__ Ah,
                                           const __nv_bfloat16* __restrict__ Al,
                                           const __nv_bfloat16* __restrict__ Bh,
                                           const __nv_bfloat16* __restrict__ Bl,
                                           int k0, int tid) {
#pragma unroll
    for (int hh = 0; hh < 2; hh++) {
        int i = tid + hh * 256;
        int row = i >> 2, c8 = i & 3;
        uint32_t so = sbase + (uint32_t)(row * SROWB + c8 * 16);
        size_t go = (size_t)row * 512 + k0 + c8 * 8;
        cp16(so,                 Ah + go);
        cp16(so + MAT_BYTES,     Al + go);
        cp16(so + 2 * MAT_BYTES, Bh + go);
        cp16(so + 3 * MAT_BYTES, Bl + go);
    }
}

// Fills acc[4][4][4]; warp tile 64x32 (wm=wid>>2, wn=wid&3).
__device__ __forceinline__ void tc_mainloop(const __nv_bfloat16* __restrict__ Ah,
                                            const __nv_bfloat16* __restrict__ Al,
                                            const __nv_bfloat16* __restrict__ Bh,
                                            const __nv_bfloat16* __restrict__ Bl,
                                            float acc[4][4][4]) {
    extern __shared__ char sm[];
    const uint32_t sbase = (uint32_t)__cvta_generic_to_shared(sm);
    const int tid = threadIdx.x;
    const int lane = tid & 31;
    const int wid = tid >> 5;
    const int wm = wid >> 2;
    const int wn = wid & 3;
    const int la = lane & 15;
    const uint32_t a_lane_off = (uint32_t)((wm * 64 + la) * SROWB + (lane >> 4) * 16);
    const int b4_row = wn * 32 + ((lane >> 4) * 8) + (lane & 7);
    const uint32_t b4_colh = (uint32_t)(((lane >> 3) & 1) * 16);

#pragma unroll
    for (int mi = 0; mi < 4; mi++)
#pragma unroll
        for (int ni = 0; ni < 4; ni++)
#pragma unroll
            for (int j = 0; j < 4; j++) acc[mi][ni][j] = 0.0f;

    stage_load(sbase, Ah, Al, Bh, Bl, 0, tid);
    cp_commit();

    for (int c = 0; c < 16; c++) {
        cp_wait<0>();
        __syncthreads();
        if (c < 15) {
            stage_load(sbase + (uint32_t)(((c + 1) & 1) * STAGE_BYTES),
                       Ah, Al, Bh, Bl, (c + 1) * BK, tid);
            cp_commit();
        }

        const uint32_t sb = sbase + (uint32_t)((c & 1) * STAGE_BYTES);
#pragma unroll
        for (int kk = 0; kk < 2; kk++) {
            // B fragments resident for this kk
            uint32_t bh[2][4], bl2[2][4];
#pragma unroll
            for (int nip = 0; nip < 2; nip++) {
                uint32_t bd = sb + 2 * MAT_BYTES +
                              (uint32_t)((b4_row + nip * 16) * SROWB) + b4_colh +
                              (uint32_t)(kk * 32);
                ldsm4(bh[nip], bd);
                ldsm4(bl2[nip], bd + MAT_BYTES);
            }
            // A fragments: double buffered across mi
            uint32_t ah[2][4], al2[2][4];
            {
                uint32_t ad0 = sb + a_lane_off + (uint32_t)(kk * 32);
                ldsm4(ah[0], ad0);
                ldsm4(al2[0], ad0 + MAT_BYTES);
            }
#pragma unroll
            for (int mi = 0; mi < 4; mi++) {
                const int cur = mi & 1, nxt = cur ^ 1;
                if (mi < 3) {
                    uint32_t adn = sb + a_lane_off +
                                   (uint32_t)((mi + 1) * 16 * SROWB + kk * 32);
                    ldsm4(ah[nxt], adn);
                    ldsm4(al2[nxt], adn + MAT_BYTES);
                }
                // pass-reordered: 4 independent MMAs between acc reuses
#pragma unroll
                for (int ni = 0; ni < 4; ni++)
                    mma16816(acc[mi][ni], ah[cur], &bh[ni >> 1][(ni & 1) * 2]);
#pragma unroll
                for (int ni = 0; ni < 4; ni++)
                    mma16816(acc[mi][ni], ah[cur], &bl2[ni >> 1][(ni & 1) * 2]);
#pragma unroll
                for (int ni = 0; ni < 4; ni++)
                    mma16816(acc[mi][ni], al2[cur], &bh[ni >> 1][(ni & 1) * 2]);
            }
        }
    }
}

// ---------------------------------------------------------------------------
// QKV GEMM -> fp32 g_qkv (plain epilogue; LN/RoPE handled downstream)
// ---------------------------------------------------------------------------
__global__ __launch_bounds__(256, 2) void gemm_qkv_tc(void) {
    const size_t bm = (size_t)blockIdx.y * 128, bn = (size_t)blockIdx.x * 128;

    float acc[4][4][4];
    tc_mainloop(g_xh + bm * 512, g_xl + bm * 512,
                g_wh + bn * 512, g_wl + bn * 512, acc);

    const int tid = threadIdx.x;
    const int lane = tid & 31;
    const int wid = tid >> 5;
    const int wm = wid >> 2, wn = wid & 3;
    const int r0 = lane >> 2, c0 = (lane & 3) * 2;
    float* C = g_qkv + bm * QKV_COLS + bn;

#pragma unroll
    for (int mi = 0; mi < 4; mi++)
#pragma unroll
        for (int ni = 0; ni < 4; ni++) {
            int row = wm * 64 + mi * 16 + r0;
            int col = wn * 32 + ni * 8 + c0;
            *(float2*)(C + (size_t)row * QKV_COLS + col) =
                make_float2(acc[mi][ni][0], acc[mi][ni][1]);
            *(float2*)(C + (size_t)(row + 8) * QKV_COLS + col) =
                make_float2(acc[mi][ni][2], acc[mi][ni][3]);
        }
}

// ---------------------------------------------------------------------------
// Output GEMM: out[b] = q[b] @ McatT[b]^T + bias
// ---------------------------------------------------------------------------
__global__ __launch_bounds__(256, 2) void gemm_out_tc(const float* __restrict__ bout,
                                                      float* __restrict__ out) {
    const int b = blockIdx.z;
    const size_t arow = (size_t)b * SEQ + (size_t)blockIdx.y * 128;
    const size_t brow = (size_t)b * DIM + (size_t)blockIdx.x * 128;

    float acc[4][4][4];
    tc_mainloop(g_qh + arow * 512, g_ql + arow * 512,
                g_mh + brow * 512, g_ml + brow * 512, acc);

    const int tid = threadIdx.x;
    const int lane = tid & 31;
    const int wid = tid >> 5;
    const int wm = wid >> 2, wn = wid & 3;
    const int r0 = lane >> 2, c0 = (lane & 3) * 2;
    float* C = out + arow * DIM + blockIdx.x * 128;
    const float* bias = bout + blockIdx.x * 128;

#pragma unroll
    for (int mi = 0; mi < 4; mi++)
#pragma unroll
        for (int ni = 0; ni < 4; ni++) {
            int row = wm * 64 + mi * 16 + r0;
            int col = wn * 32 + ni * 8 + c0;
            float b0 = bias[col], b1 = bias[col + 1];
            *(float2*)(C + (size_t)row * DIM + col) =
                make_float2(acc[mi][ni][0] + b0, acc[mi][ni][1] + b1);
            *(float2*)(C + (size_t)(row + 8) * DIM + col) =
                make_float2(acc[mi][ni][2] + b0, acc[mi][ni][3] + b1);
        }
}

// ---------------------------------------------------------------------------
// bf16 hi/lo split (x and Wqkv)
// ---------------------------------------------------------------------------
__global__ __launch_bounds__(256) void split_kernel(const float* __restrict__ src,
                                                    __nv_bfloat16* __restrict__ hi,
                                                    __nv_bfloat16* __restrict__ lo,
                                                    int n4) {
    int i = blockIdx.x * 256 + threadIdx.x;
    if (i >= n4) return;
    float4 v = ((const float4*)src)[i];
    size_t idx = (size_t)i * 4;
    __nv_bfloat16 hx = __float2bfloat16(v.x), hy = __float2bfloat16(v.y);
    __nv_bfloat16 hz = __float2bfloat16(v.z), hw = __float2bfloat16(v.w);
    hi[idx + 0] = hx; hi[idx + 1] = hy; hi[idx + 2] = hz; hi[idx + 3] = hw;
    lo[idx + 0] = __float2bfloat16(v.x - __bfloat162float(hx));
    lo[idx + 1] = __float2bfloat16(v.y - __bfloat162float(hy));
    lo[idx + 2] = __float2bfloat16(v.z - __bfloat162float(hz));
    lo[idx + 3] = __float2bfloat16(v.w - __bfloat162float(hw));
}

// ---------------------------------------------------------------------------
// LN(k,v) + RoPE(q,k) reading fp32 g_qkv, writing bf16 hi/lo q/k/v directly.
// One warp per (b,n,h) row.
// ---------------------------------------------------------------------------
__global__ __launch_bounds__(256) void ln_rope_split_kernel(
        const float* __restrict__ pos,
        const float* __restrict__ gk, const float* __restrict__ bk,
        const float* __restrict__ gv, const float* __restrict__ bv) {
    const int warp = threadIdx.x >> 5;
    const int lane = threadIdx.x & 31;
    const int r = blockIdx.x * 8 + warp;     // 0 .. B*N*H-1
    const int b = r >> 15;
    const int rem = r & 32767;
    const int n = rem >> 3;
    const int h = rem & 7;
    const int token = b * SEQ + n;

    const float* qp = g_qkv + (size_t)token * QKV_COLS + h * DH;
    const float* kp = qp + INNER;
    const float* vp = qp + 2 * INNER;

    float q0 = qp[lane], q1 = qp[lane + 32];
    float k0 = kp[lane], k1 = kp[lane + 32];
    float v0 = vp[lane], v1 = vp[lane + 32];

    // LayerNorm k
    float mu = warp_sum(k0 + k1) * (1.0f / 64.0f);
    float d0 = k0 - mu, d1 = k1 - mu;
    float var = warp_sum(d0 * d0 + d1 * d1) * (1.0f / 64.0f);
    float inv = rsqrtf(var + EPS);
    k0 = d0 * inv * gk[lane] + bk[lane];
    k1 = d1 * inv * gk[lane + 32] + bk[lane + 32];

    // LayerNorm v
    mu = warp_sum(v0 + v1) * (1.0f / 64.0f);
    d0 = v0 - mu; d1 = v1 - mu;
    var = warp_sum(d0 * d0 + d1 * d1) * (1.0f / 64.0f);
    inv = rsqrtf(var + EPS);
    v0 = d0 * inv * gv[lane] + bv[lane];
    v1 = d1 * inv * gv[lane + 32] + bv[lane + 32];

    // 2D RoPE on q,k
    const float cxp = pos[(size_t)token * 2 + 0];
    const float cyp = pos[(size_t)token * 2 + 1];
    float invf = exp2f(-0.830482023721841f * (float)(lane & 15)) * 64.0f;
    float sx, cx, sy, cy;
    sincosf(cxp * invf, &sx, &cx);
    sincosf(cyp * invf, &sy, &cy);
    const float sgn = (lane < 16) ? -1.0f : 1.0f;

    float qp0 = __shfl_xor_sync(0xffffffffu, q0, 16);
    float qp1 = __shfl_xor_sync(0xffffffffu, q1, 16);
    float kp0 = __shfl_xor_sync(0xffffffffu, k0, 16);
    float kp1 = __shfl_xor_sync(0xffffffffu, k1, 16);
    q0 = q0 * cx + sgn * qp0 * sx;
    q1 = q1 * cy + sgn * qp1 * sy;
    k0 = k0 * cx + sgn * kp0 * sx;
    k1 = k1 * cy + sgn * kp1 * sy;

    // write bf16 hi/lo, layout token*512 + h*64 + d
    const size_t base = (size_t)token * 512 + h * DH;
#define WR(arr_h, arr_l, a0, a1)                                            \
    {                                                                       \
        __nv_bfloat16 h0 = __float2bfloat16(a0);                            \
        __nv_bfloat16 h1 = __float2bfloat16(a1);                            \
        arr_h[base + lane] = h0;                                            \
        arr_h[base + 32 + lane] = h1;                                       \
        arr_l[base + lane] = __float2bfloat16(a0 - __bfloat162float(h0));   \
        arr_l[base + 32 + lane] = __float2bfloat16(a1 - __bfloat162float(h1)); \
    }
    WR(g_qh, g_ql, q0, q1)
    WR(g_kh, g_kl, k0, k1)
    WR(g_vh, g_vl, v0, v1)
#undef WR
}

// ---------------------------------------------------------------------------
// dots = K^T V via HMMA (3-pass split), K-major loads via ldmatrix.trans.
// grid (64 bh, 4 splits of 1024 tokens). 128 threads = 4 warps (2x2 of 32x32).
// ---------------------------------------------------------------------------
#define KV_SR 72                       // bf16 elems per row = 144B
#define KV_TILE (64 * KV_SR * 2)       // 9216
#define KV_STAGE (4 * KV_TILE)         // 36864
#define KV_SMEM (3 * KV_STAGE)         // 110592

__device__ __forceinline__ void kv_stage_load(uint32_t sb, int b, int h, int tok0,
                                              int tid) {
#pragma unroll
    for (int hh = 0; hh < 16; hh++) {
        int i = tid + hh * 128;        // 0..2047
        int op = i >> 9;
        int ii = i & 511;
        int row = ii >> 3, ch = ii & 7;
        const __nv_bfloat16* src = (op == 0) ? g_kh : (op == 1) ? g_kl
                                 : (op == 2) ? g_vh : g_vl;
        cp16(sb + (uint32_t)(op * KV_TILE + row * (KV_SR * 2) + ch * 16),
             src + ((size_t)(b * SEQ + tok0 + row)) * 512 + h * 64 + ch * 8);
    }
}

__global__ __launch_bounds__(128) void kv_dots_kernel() {
    extern __shared__ char sm[];
    const uint32_t sbase = (uint32_t)__cvta_generic_to_shared(sm);
    const int bh = blockIdx.x;
    const int b = bh >> 3, h = bh & 7;
    const int tok0 = blockIdx.y * 1024;
    const int tid = threadIdx.x;
    const int lane = tid & 31;
    const int wid = tid >> 5;
    const int wm = wid >> 1;
    const int wn = wid & 1;

    const int t_row = (lane & 7) + ((lane >> 4) & 1) * 8;
    const int a_col = ((lane >> 3) & 1) * 8;
    const int b_row = (lane & 7) + ((lane >> 3) & 1) * 8;
    const int b_col = (lane >> 4) * 8;

    float acc[2][4][4];
#pragma unroll
    for (int mf = 0; mf < 2; mf++)
#pragma unroll
        for (int nf = 0; nf < 4; nf++)
#pragma unroll
            for (int j = 0; j < 4; j++) acc[mf][nf][j] = 0.0f;

    kv_stage_load(sbase, b, h, tok0, tid);
    cp_commit();
    kv_stage_load(sbase + KV_STAGE, b, h, tok0 + 64, tid);
    cp_commit();

    for (int s = 0; s < 16; s++) {
        if (s < 15) cp_wait<1>(); else cp_wait<0>();
        __syncthreads();
        if (s + 2 < 16) {
            kv_stage_load(sbase + (uint32_t)(((s + 2) % 3) * KV_STAGE),
                          b, h, tok0 + (s + 2) * 64, tid);
            cp_commit();
        }
        const uint32_t sb = sbase + (uint32_t)((s % 3) * KV_STAGE);
#pragma unroll
        for (int kt = 0; kt < 4; kt++) {
            const int kt0 = kt * 16;
            uint32_t aH[2][4], aL[2][4], bH[2][4], bL[2][4];
#pragma unroll
            for (int mf = 0; mf < 2; mf++) {
                int d0 = wm * 32 + mf * 16;
                uint32_t ad = sb + (uint32_t)((kt0 + t_row) * (KV_SR * 2) +
                                              (d0 + a_col) * 2);
                ldsm4t(aH[mf], ad);
                ldsm4t(aL[mf], ad + KV_TILE);
            }
#pragma unroll
            for (int g = 0; g < 2; g++) {
                int e0 = wn * 32 + g * 16;
                uint32_t bd = sb + 2 * KV_TILE +
                              (uint32_t)((kt0 + b_row) * (KV_SR * 2) +
                                         (e0 + b_col) * 2);
                ldsm4t(bH[g], bd);
                ldsm4t(bL[g], bd + KV_TILE);
            }
#pragma unroll
            for (int mf = 0; mf < 2; mf++)
#pragma unroll
                for (int nf = 0; nf < 4; nf++) {
                    const uint32_t* bhf = &bH[nf >> 1][(nf & 1) * 2];
                    const uint32_t* blf = &bL[nf >> 1][(nf & 1) * 2];
                    mma16816(acc[mf][nf], aH[mf], bhf);
                    mma16816(acc[mf][nf], aH[mf], blf);
                    mma16816(acc[mf][nf], aL[mf], bhf);
                }
        }
    }

    float* dbase = g_dots + (size_t)bh * DH * DH;
    const int r0 = lane >> 2, c0 = (lane & 3) * 2;
#pragma unroll
    for (int mf = 0; mf < 2; mf++)
#pragma unroll
        for (int nf = 0; nf < 4; nf++) {
            int d = wm * 32 + mf * 16 + r0;
            int e = wn * 32 + nf * 8 + c0;
            atomicAdd(&dbase[d * DH + e],       acc[mf][nf][0]);
            atomicAdd(&dbase[d * DH + e + 1],   acc[mf][nf][1]);
            atomicAdd(&dbase[(d + 8) * DH + e],     acc[mf][nf][2]);
            atomicAdd(&dbase[(d + 8) * DH + e + 1], acc[mf][nf][3]);
        }
}

__global__ void zero_dots_kernel() {
    g_dots[blockIdx.x * blockDim.x + threadIdx.x] = 0.0f;
}

// ---------------------------------------------------------------------------
// McatT[b][o, h*64+d] = (1/SEQ) * sum_e dots[b,h,d,e] * Wout[o, h*64+e]
// ---------------------------------------------------------------------------
__global__ __launch_bounds__(256) void mcat_kernel(const float* __restrict__ Wout) {
    __shared__ float ds[64][65];
    __shared__ float ws[64][65];

    const int bh = blockIdx.x;
    const int b = bh >> 3, h = bh & 7;
    const int o0 = blockIdx.y * 64;
    const int tid = threadIdx.x;

    for (int i = tid; i < 4096; i += 256) {
        int d = i >> 6, e = i & 63;
        ds[d][e] = g_dots[(size_t)bh * 4096 + i];
        ws[d][e] = Wout[(size_t)(o0 + d) * INNER + h * DH + e];
    }
    __syncthreads();

    for (int t = tid; t < 4096; t += 256) {
        int oL = t >> 6, d = t & 63;
        float acc = 0.0f;
#pragma unroll
        for (int e = 0; e < 64; e++) acc += ds[d][e] * ws[oL][e];
        acc *= (1.0f / (float)SEQ);
        size_t idx = ((size_t)b * DIM + (o0 + oL)) * 512 + h * DH + d;
        __nv_bfloat16 hi = __float2bfloat16(acc);
        g_mh[idx] = hi;
        g_ml[idx] = __float2bfloat16(acc - __bfloat162float(hi));
    }
}

// ---------------------------------------------------------------------------
// launch
// ---------------------------------------------------------------------------
extern "C" void kernel_launch(void* const* d_in, const int* in_sizes, int n_in,
                              void* d_out, int out_size) {
    const float* x    = (const float*)d_in[0];
    const float* pos  = (const float*)d_in[1];
    const float* Wqkv = (const float*)d_in[2];
    const float* gk   = (const float*)d_in[3];
    const float* bk   = (const float*)d_in[4];
    const float* gv   = (const float*)d_in[5];
    const float* bv   = (const float*)d_in[6];
    const float* Wout = (const float*)d_in[7];
    const float* bout = (const float*)d_in[8];
    float* out = (float*)d_out;

    static bool attr_done = false;
    if (!attr_done) {
        cudaFuncSetAttribute(gemm_qkv_tc,  cudaFuncAttributeMaxDynamicSharedMemorySize, GEMM_SMEM);
        cudaFuncSetAttribute(gemm_out_tc,  cudaFuncAttributeMaxDynamicSharedMemorySize, GEMM_SMEM);
        cudaFuncSetAttribute(kv_dots_kernel, cudaFuncAttributeMaxDynamicSharedMemorySize, KV_SMEM);
        attr_done = true;
    }

    void* p_xh; void* p_xl; void* p_wh; void* p_wl;
    cudaGetSymbolAddress(&p_xh, g_xh); cudaGetSymbolAddress(&p_xl, g_xl);
    cudaGetSymbolAddress(&p_wh, g_wh); cudaGetSymbolAddress(&p_wl, g_wl);

    // 1) hi/lo splits + dots zero
    int n4x = (ROWS * DIM) / 4;
    split_kernel<<<(n4x + 255) / 256, 256>>>(x, (__nv_bfloat16*)p_xh,
                                             (__nv_bfloat16*)p_xl, n4x);
    int n4w = (QKV_COLS * DIM) / 4;
    split_kernel<<<(n4w + 255) / 256, 256>>>(Wqkv, (__nv_bfloat16*)p_wh,
                                             (__nv_bfloat16*)p_wl, n4w);
    zero_dots_kernel<<<(BATCH * HEADS * DH * DH) / 256, 256>>>();

    // 2) qkv = x @ Wqkv^T (HMMA split-bf16) -> fp32 g_qkv
    gemm_qkv_tc<<<dim3(QKV_COLS / 128, ROWS / 128), 256, GEMM_SMEM>>>();

    // 3) LN(k,v) + RoPE(q,k) + hi/lo split -> g_{q,k,v}{h,l}
    ln_rope_split_kernel<<<(BATCH * SEQ * HEADS) / 8, 256>>>(pos, gk, bk, gv, bv);

    // 4) dots = K^T V (HMMA, atomic over 4 splits)
    kv_dots_kernel<<<dim3(BATCH * HEADS, 4), 128, KV_SMEM>>>();

    // 5) McatT[b] = (dots[b] @ Wout^T)/SEQ (bf16 hi/lo)
    mcat_kernel<<<dim3(BATCH * HEADS, DIM / 64), 256>>>(Wout);

    // 6) out[b] = q[b] @ McatT[b]^T + b_out
    gemm_out_tc<<<dim3(DIM / 128, SEQ / 128, BATCH), 256, GEMM_SMEM>>>(bout, out);
}